// round 16
// baseline (speedup 1.0000x reference)
#include <cuda_runtime.h>
#include <cuda_fp16.h>
#include <cstdint>
#include <cstddef>

#define NN    8192
#define NCOL  768
#define BM    128
#define BN    128
#define BK    64
#define THREADS 256
#define STAGES 3
#define NSPLIT 3
#define A_STAGE_BYTES (BM * BK * 2)                   // 16384
#define B_STAGE_BYTES (BN * BK * 2)                   // 16384
#define STAGE_BYTES   (A_STAGE_BYTES + B_STAGE_BYTES) // 32768
#define SMEM_BYTES    (STAGES * STAGE_BYTES)          // 98304

// scratch (static device globals: allocation-free per harness rules)
__device__ __half g_Ah [(size_t)NN * NN];             // fp16 (adj + I), K-major
__device__ __half g_ZTh[(size_t)NCOL * NN];           // (X@W)^T fp16 (K-major B operand)
__device__ __half g_Ph [NSPLIT * (size_t)NN * NCOL];  // split-K partials (fp16)
__device__ float  g_invdeg[NN];

// ---------------------------------------------------------------------------
// helpers
// ---------------------------------------------------------------------------
__device__ __forceinline__ void cp16(uint32_t smem_addr, const void* gptr) {
    asm volatile("cp.async.cg.shared.global [%0], [%1], 16;\n"
                 :: "r"(smem_addr), "l"(gptr));
}

__device__ __forceinline__ void ldm_x4(uint32_t& r0, uint32_t& r1, uint32_t& r2,
                                       uint32_t& r3, uint32_t addr) {
    asm volatile("ldmatrix.sync.aligned.m8n8.x4.shared.b16 {%0,%1,%2,%3}, [%4];"
                 : "=r"(r0), "=r"(r1), "=r"(r2), "=r"(r3) : "r"(addr));
}

__device__ __forceinline__ void mma_fp16(float* c, const uint32_t* a, const uint32_t* b) {
    asm volatile(
        "mma.sync.aligned.m16n8k16.row.col.f32.f16.f16.f32 "
        "{%0,%1,%2,%3}, {%4,%5,%6,%7}, {%8,%9}, {%0,%1,%2,%3};\n"
        : "+f"(c[0]), "+f"(c[1]), "+f"(c[2]), "+f"(c[3])
        : "r"(a[0]), "r"(a[1]), "r"(a[2]), "r"(a[3]), "r"(b[0]), "r"(b[1]));
}

// ---------------------------------------------------------------------------
// Kernel 1: A_half = fp16(adj + I)  AND  inv_deg[i] = 1/rowsum(A+I)
// (separate launch — measured faster than any fused-grid variant)
// ---------------------------------------------------------------------------
__global__ void degconv_kernel(const float* __restrict__ adj) {
    __shared__ float red[256];
    const int row = blockIdx.x;
    const float4* p = reinterpret_cast<const float4*>(adj + (size_t)row * NN);
    uint2* o = reinterpret_cast<uint2*>(g_Ah + (size_t)row * NN);
    const int diag4 = row >> 2;    // float4 index containing the diagonal
    float s = 0.f;
#pragma unroll
    for (int i = 0; i < (NN / 4) / 256; i++) {
        const int idx = threadIdx.x + i * 256;
        float4 v = p[idx];
        if (idx == diag4) reinterpret_cast<float*>(&v)[row & 3] += 1.0f;  // self-loop
        s += (v.x + v.y) + (v.z + v.w);
        __half2 h0 = __floats2half2_rn(v.x, v.y);
        __half2 h1 = __floats2half2_rn(v.z, v.w);
        uint2 u;
        u.x = *reinterpret_cast<const unsigned*>(&h0);
        u.y = *reinterpret_cast<const unsigned*>(&h1);
        o[idx] = u;
    }
    red[threadIdx.x] = s;
    __syncthreads();
    for (int off = 128; off > 0; off >>= 1) {
        if (threadIdx.x < off) red[threadIdx.x] += red[threadIdx.x + off];
        __syncthreads();
    }
    if (threadIdx.x == 0) g_invdeg[row] = 1.0f / red[0];
}

// ---------------------------------------------------------------------------
// Kernel 2: ZTh = fp16((X @ W)^T)   [768, 8192]  (no fp32 Z round-trip)
// ---------------------------------------------------------------------------
__global__ void xwt_kernel(const float* __restrict__ X, const float* __restrict__ W) {
    __shared__ float Ws[32][33];
    __shared__ float Xs[32][33];
    const int n0  = blockIdx.x * 32;
    const int tid = threadIdx.x;        // 256
    const int node = tid & 31;
    const int og   = tid >> 5;          // 0..7

    for (int i = tid; i < 1024; i += 256) Ws[i >> 5][i & 31] = W[i];

    for (int t = 0; t < 24; t++) {
        __syncthreads();   // protect Xs reuse from previous t's readers
#pragma unroll
        for (int rr = 0; rr < 4; rr++) {
            const int n = og + rr * 8;
            Xs[n][node] = X[(size_t)(n0 + n) * NCOL + t * 32 + node];
        }
        __syncthreads();
#pragma unroll
        for (int osub = 0; osub < 4; osub++) {
            const int o = og * 4 + osub;
            float acc = 0.f;
#pragma unroll
            for (int a = 0; a < 32; a++) acc += Xs[node][a] * Ws[a][o];
            g_ZTh[(size_t)(t * 32 + o) * NN + n0 + node] = __float2half(acc);
        }
    }
}

// ---------------------------------------------------------------------------
// Kernel 3: fp16 tensor GEMM, split-K=3 (43/43/42 chunks of 64).
// CTA tile 128x128, 3-stage cp.async, one barrier per K-chunk, 8 warps 2x4,
// 2 CTAs/SM. Warp-skewed k16-step order with SMSP-distinct phases
// (phase = (warp + (warp>>2)) & 3 so warps w and w+4 — which share a
// scheduler — run different phases). XOR-hoisted ldmatrix swizzle;
// fully-hoisted loader addressing (immediate-offset cp.async).
// ---------------------------------------------------------------------------
__global__ void __launch_bounds__(THREADS, 2)
gemm_kernel(float* __restrict__ dummy) {
    extern __shared__ char smem[];

    const int tid  = threadIdx.x;
    const int lane = tid & 31;
    const int warp = tid >> 5;
    const int m0 = blockIdx.y * BM;
    const int n0 = blockIdx.x * BN;
    const int k0  = blockIdx.z * 2752;                 // split K offset (elements)
    const int NKC = (blockIdx.z == 2) ? 42 : 43;       // 64-wide chunks in this split

    const uint32_t sbase = (uint32_t)__cvta_generic_to_shared(smem);

    // ---- hoisted loader state ----
    const uint32_t r0  = (uint32_t)tid >> 3;
    const uint32_t c16 = ((uint32_t)tid & 7u) << 4;
    const uint32_t adrel = r0 * 128u + (c16 ^ ((r0 & 7u) << 4));   // swizzled base
    const __half* pA = g_Ah  + (size_t)m0 * NN + k0 + (size_t)r0 * NN + (tid & 7) * 8;
    const __half* pB = g_ZTh + (size_t)n0 * NN + k0 + (size_t)r0 * NN + (tid & 7) * 8;
    uint32_t stoff = 0;                                // rotating stage byte offset

    auto load_stage = [&]() {
        const uint32_t base = sbase + stoff + adrel;
#pragma unroll
        for (int j = 0; j < 8; j++) {
            const __half* src = (j < 4 ? pA : pB) + (size_t)(j & 3) * 32 * NN;
            const uint32_t dst = base + (j < 4 ? 0u : (uint32_t)A_STAGE_BYTES)
                                      + (uint32_t)(j & 3) * 4096u;
            cp16(dst, src);
        }
        pA += BK;
        pB += BK;
        stoff = (stoff == 2 * STAGE_BYTES) ? 0u : stoff + STAGE_BYTES;
        asm volatile("cp.async.commit_group;\n" ::);
    };

    float acc[4][4][4];
#pragma unroll
    for (int mi = 0; mi < 4; mi++)
#pragma unroll
        for (int ni = 0; ni < 4; ni++)
#pragma unroll
            for (int c = 0; c < 4; c++) acc[mi][ni][c] = 0.f;

    const int wm = (warp >> 2) * 64;   // warp M offset (2 rows)
    const int wn = (warp & 3) * 32;    // warp N offset (4 cols)

    // ---- hoisted ldmatrix base offsets (s-independent part) ----
    uint32_t aoff[4], boff[2];
#pragma unroll
    for (int mi = 0; mi < 4; mi++) {
        const uint32_t row = (uint32_t)(wm + mi * 16 + (lane & 15));
        const uint32_t cc = ((uint32_t)lane >> 4) << 4;
        aoff[mi] = row * 128u + (cc ^ ((row & 7u) << 4));
    }
#pragma unroll
    for (int nj = 0; nj < 2; nj++) {
        const uint32_t row = (uint32_t)(wn + nj * 16 + (lane >> 4) * 8 + (lane & 7));
        const uint32_t cc = (((uint32_t)lane >> 3) & 1u) << 4;
        boff[nj] = row * 128u + (cc ^ ((row & 7u) << 4));
    }

    // SMSP-distinct skew phase: warps w and w+4 share a scheduler; offset them.
    const int ph = (warp + (warp >> 2)) & 3;

    load_stage();
    load_stage();

    uint32_t st_rd = 0;   // read-stage byte offset (rotates like stoff)
    for (int kc = 0; kc < NKC; kc++) {
        if (kc + 1 < NKC) {
            asm volatile("cp.async.wait_group 1;\n" ::);
        } else {
            asm volatile("cp.async.wait_group 0;\n" ::);
        }
        __syncthreads();

        const uint32_t Ab = sbase + st_rd;
        const uint32_t Bb = Ab + A_STAGE_BYTES;
        st_rd = (st_rd == 2 * STAGE_BYTES) ? 0u : st_rd + STAGE_BYTES;
#pragma unroll
        for (int si = 0; si < 4; si++) {       // k16 steps, warp-skewed order
            const uint32_t sx = (uint32_t)(((si + ph) & 3) << 5);
            uint32_t a[4][4];
#pragma unroll
            for (int mi = 0; mi < 4; mi++)
                ldm_x4(a[mi][0], a[mi][1], a[mi][2], a[mi][3], Ab + (aoff[mi] ^ sx));
            uint32_t b[4][2];
#pragma unroll
            for (int nj = 0; nj < 2; nj++)
                ldm_x4(b[nj * 2][0], b[nj * 2][1], b[nj * 2 + 1][0], b[nj * 2 + 1][1],
                       Bb + (boff[nj] ^ sx));
#pragma unroll
            for (int mi = 0; mi < 4; mi++)
#pragma unroll
                for (int ni = 0; ni < 4; ni++)
                    mma_fp16(acc[mi][ni], a[mi], b[ni]);

            // defer next-stage cp.async issue until after this warp's first
            // compute step: LSU burst overlaps other warps' tensor work.
            // stage being overwritten was last read at iter kc-1; every warp
            // has passed the barrier above since, so this is race-free.
            if (si == 0 && kc + 2 < NKC) load_stage();
        }
    }

    // ---- store fp16 partials for this split ----
    __half* P = g_Ph + (size_t)blockIdx.z * NN * NCOL;
    const int lr = lane >> 2;
    const int lc = lane & 3;
#pragma unroll
    for (int mi = 0; mi < 4; mi++) {
        const int row0 = m0 + wm + mi * 16 + lr;
        const int row1 = row0 + 8;
#pragma unroll
        for (int ni = 0; ni < 4; ni++) {
            const int col = n0 + wn + ni * 8 + lc * 2;
            const __half2 h0 = __floats2half2_rn(acc[mi][ni][0], acc[mi][ni][1]);
            const __half2 h1 = __floats2half2_rn(acc[mi][ni][2], acc[mi][ni][3]);
            *reinterpret_cast<__half2*>(&P[(size_t)row0 * NCOL + col]) = h0;
            *reinterpret_cast<__half2*>(&P[(size_t)row1 * NCOL + col]) = h1;
        }
    }
}

// ---------------------------------------------------------------------------
// Kernel 4: out = (P0 + P1 + P2) * inv_deg + bias   (self-loop is inside A+I)
// ---------------------------------------------------------------------------
__global__ void combine_kernel(const float* __restrict__ bias, float* __restrict__ out) {
    __shared__ float biasS[32];
    if (threadIdx.x < 32) biasS[threadIdx.x] = bias[threadIdx.x];
    __syncthreads();
    const int idx = blockIdx.x * blockDim.x + threadIdx.x;     // 4-col group index
    const int row = idx / (NCOL / 4);
    const int c4  = (idx % (NCOL / 4)) * 4;
    const size_t off = (size_t)row * NCOL + c4;
    const __half2* p0 = reinterpret_cast<const __half2*>(g_Ph + off);
    const __half2* p1 = reinterpret_cast<const __half2*>(g_Ph + (size_t)NN * NCOL + off);
    const __half2* p2 = reinterpret_cast<const __half2*>(g_Ph + 2 * (size_t)NN * NCOL + off);
    const float id = g_invdeg[row];
    float4 o;
    {
        const float2 a = __half22float2(p0[0]);
        const float2 b = __half22float2(p1[0]);
        const float2 c = __half22float2(p2[0]);
        o.x = (a.x + b.x + c.x) * id + biasS[(c4 + 0) & 31];
        o.y = (a.y + b.y + c.y) * id + biasS[(c4 + 1) & 31];
    }
    {
        const float2 a = __half22float2(p0[1]);
        const float2 b = __half22float2(p1[1]);
        const float2 c = __half22float2(p2[1]);
        o.z = (a.x + b.x + c.x) * id + biasS[(c4 + 2) & 31];
        o.w = (a.y + b.y + c.y) * id + biasS[(c4 + 3) & 31];
    }
    *reinterpret_cast<float4*>(out + off) = o;
}

// ---------------------------------------------------------------------------
extern "C" void kernel_launch(void* const* d_in, const int* in_sizes, int n_in,
                              void* d_out, int out_size) {
    const float* X    = (const float*)d_in[0];   // node_feats [8192,24,32]
    const float* adj  = (const float*)d_in[1];   // adj_matrix [8192,8192]
    const float* W    = (const float*)d_in[2];   // weight [32,32]
    const float* bias = (const float*)d_in[3];   // bias [32]
    float* out = (float*)d_out;

    cudaFuncSetAttribute(gemm_kernel, cudaFuncAttributeMaxDynamicSharedMemorySize,
                         SMEM_BYTES);

    degconv_kernel<<<NN, 256>>>(adj);
    xwt_kernel<<<NN / 32, 256>>>(X, W);
    gemm_kernel<<<dim3(NCOL / BN, NN / BM, NSPLIT), THREADS, SMEM_BYTES>>>(out);
    combine_kernel<<<(NN * NCOL / 4) / 256, 256>>>(bias, out);
}

// round 17
// speedup vs baseline: 1.1072x; 1.1072x over previous
#include <cuda_runtime.h>
#include <cuda_fp16.h>
#include <cstdint>
#include <cstddef>

#define NN    8192
#define NCOL  768
#define BM    128
#define BN    128
#define BK    64
#define THREADS 256
#define STAGES 3
#define NSPLIT 3
#define A_STAGE_BYTES (BM * BK * 2)                   // 16384
#define B_STAGE_BYTES (BN * BK * 2)                   // 16384
#define STAGE_BYTES   (A_STAGE_BYTES + B_STAGE_BYTES) // 32768
#define SMEM_BYTES    (STAGES * STAGE_BYTES)          // 98304

// scratch (static device globals: allocation-free per harness rules)
__device__ __half g_Ah [(size_t)NN * NN];             // fp16 (adj + I), K-major
__device__ __half g_ZTh[(size_t)NCOL * NN];           // (X@W)^T fp16 (K-major B operand)
__device__ __half g_Ph [NSPLIT * (size_t)NN * NCOL];  // split-K partials (fp16)
__device__ float  g_invdeg[NN];

// ---------------------------------------------------------------------------
// helpers
// ---------------------------------------------------------------------------
__device__ __forceinline__ void cp16(uint32_t smem_addr, const void* gptr) {
    asm volatile("cp.async.cg.shared.global [%0], [%1], 16;\n"
                 :: "r"(smem_addr), "l"(gptr));
}

__device__ __forceinline__ void ldm_x4(uint32_t& r0, uint32_t& r1, uint32_t& r2,
                                       uint32_t& r3, uint32_t addr) {
    asm volatile("ldmatrix.sync.aligned.m8n8.x4.shared.b16 {%0,%1,%2,%3}, [%4];"
                 : "=r"(r0), "=r"(r1), "=r"(r2), "=r"(r3) : "r"(addr));
}

__device__ __forceinline__ void mma_fp16(float* c, const uint32_t* a, const uint32_t* b) {
    asm volatile(
        "mma.sync.aligned.m16n8k16.row.col.f32.f16.f16.f32 "
        "{%0,%1,%2,%3}, {%4,%5,%6,%7}, {%8,%9}, {%0,%1,%2,%3};\n"
        : "+f"(c[0]), "+f"(c[1]), "+f"(c[2]), "+f"(c[3])
        : "r"(a[0]), "r"(a[1]), "r"(a[2]), "r"(a[3]), "r"(b[0]), "r"(b[1]));
}

// ---------------------------------------------------------------------------
// Kernel 1 (fused pre-processing, one launch — R13 champion layout):
//   blocks [0, 256):    ZTh = fp16((X@W)^T)            (no dependency on adj)
//   blocks [256, 8448): A_half = fp16(adj + I), inv_deg = 1/rowsum(A+I)
// xwt blocks FIRST in the grid so they co-schedule with wave-1 degconv
// blocks and hide under the DRAM-bound adjacency scan.
// ---------------------------------------------------------------------------
__global__ void pre_kernel(const float* __restrict__ adj,
                           const float* __restrict__ X,
                           const float* __restrict__ W) {
    __shared__ float red[256];      // degconv reduction
    __shared__ float Ws[32][33];    // xwt weight tile
    __shared__ float Xs[32][33];    // xwt node-feature tile

    const int tid = threadIdx.x;    // 256

    if (blockIdx.x < 256) {
        // ---------------- xwt: 32 nodes per block ----------------
        const int n0   = blockIdx.x * 32;
        const int node = tid & 31;
        const int og   = tid >> 5;          // 0..7

        for (int i = tid; i < 1024; i += 256) Ws[i >> 5][i & 31] = W[i];

        for (int t = 0; t < 24; t++) {
            __syncthreads();   // protect Xs reuse from previous t's readers
#pragma unroll
            for (int rr = 0; rr < 4; rr++) {
                const int n = og + rr * 8;
                Xs[n][node] = X[(size_t)(n0 + n) * NCOL + t * 32 + node];
            }
            __syncthreads();
#pragma unroll
            for (int osub = 0; osub < 4; osub++) {
                const int o = og * 4 + osub;
                float acc = 0.f;
#pragma unroll
                for (int a = 0; a < 32; a++) acc += Xs[node][a] * Ws[a][o];
                g_ZTh[(size_t)(t * 32 + o) * NN + n0 + node] = __float2half(acc);
            }
        }
        return;
    }

    // ---------------- degconv: one adjacency row per block ----------------
    const int row = blockIdx.x - 256;
    const float4* p = reinterpret_cast<const float4*>(adj + (size_t)row * NN);
    uint2* o = reinterpret_cast<uint2*>(g_Ah + (size_t)row * NN);
    const int diag4 = row >> 2;    // float4 index containing the diagonal
    float s = 0.f;
#pragma unroll
    for (int i = 0; i < (NN / 4) / 256; i++) {
        const int idx = tid + i * 256;
        float4 v = p[idx];
        if (idx == diag4) reinterpret_cast<float*>(&v)[row & 3] += 1.0f;  // self-loop
        s += (v.x + v.y) + (v.z + v.w);
        __half2 h0 = __floats2half2_rn(v.x, v.y);
        __half2 h1 = __floats2half2_rn(v.z, v.w);
        uint2 u;
        u.x = *reinterpret_cast<const unsigned*>(&h0);
        u.y = *reinterpret_cast<const unsigned*>(&h1);
        o[idx] = u;
    }
    red[tid] = s;
    __syncthreads();
    for (int off = 128; off > 0; off >>= 1) {
        if (tid < off) red[tid] += red[tid + off];
        __syncthreads();
    }
    if (tid == 0) g_invdeg[row] = 1.0f / red[0];
}

// ---------------------------------------------------------------------------
// Kernel 2: fp16 tensor GEMM, split-K=3 (43/43/42 chunks of 64).
// CTA tile 128x128, 3-stage cp.async, one barrier per K-chunk, 8 warps 2x4,
// 2 CTAs/SM. Warp-skewed k16-step order with SMSP-distinct phases.
// XOR-hoisted ldmatrix swizzle; fully-hoisted loader addressing.
// NEW: the deferred next-stage load is issued in TWO half-bursts (A rows
// after s-step 0, B rows + commit after s-step 1) to halve the LSU queue
// spike per warp.
// ---------------------------------------------------------------------------
__global__ void __launch_bounds__(THREADS, 2)
gemm_kernel(float* __restrict__ dummy) {
    extern __shared__ char smem[];

    const int tid  = threadIdx.x;
    const int lane = tid & 31;
    const int warp = tid >> 5;
    const int m0 = blockIdx.y * BM;
    const int n0 = blockIdx.x * BN;
    const int k0  = blockIdx.z * 2752;                 // split K offset (elements)
    const int NKC = (blockIdx.z == 2) ? 42 : 43;       // 64-wide chunks in this split

    const uint32_t sbase = (uint32_t)__cvta_generic_to_shared(smem);

    // ---- hoisted loader state ----
    const uint32_t r0  = (uint32_t)tid >> 3;
    const uint32_t c16 = ((uint32_t)tid & 7u) << 4;
    const uint32_t adrel = r0 * 128u + (c16 ^ ((r0 & 7u) << 4));   // swizzled base
    const __half* pA = g_Ah  + (size_t)m0 * NN + k0 + (size_t)r0 * NN + (tid & 7) * 8;
    const __half* pB = g_ZTh + (size_t)n0 * NN + k0 + (size_t)r0 * NN + (tid & 7) * 8;
    uint32_t stoff = 0;                                // rotating stage byte offset

    auto load_half_A = [&]() {
        const uint32_t base = sbase + stoff + adrel;
#pragma unroll
        for (int j = 0; j < 4; j++)
            cp16(base + (uint32_t)j * 4096u, pA + (size_t)j * 32 * NN);
    };
    auto load_half_B = [&]() {   // also commits and advances loader state
        const uint32_t base = sbase + stoff + adrel + (uint32_t)A_STAGE_BYTES;
#pragma unroll
        for (int j = 0; j < 4; j++)
            cp16(base + (uint32_t)j * 4096u, pB + (size_t)j * 32 * NN);
        pA += BK;
        pB += BK;
        stoff = (stoff == 2 * STAGE_BYTES) ? 0u : stoff + STAGE_BYTES;
        asm volatile("cp.async.commit_group;\n" ::);
    };
    auto load_stage = [&]() { load_half_A(); load_half_B(); };

    float acc[4][4][4];
#pragma unroll
    for (int mi = 0; mi < 4; mi++)
#pragma unroll
        for (int ni = 0; ni < 4; ni++)
#pragma unroll
            for (int c = 0; c < 4; c++) acc[mi][ni][c] = 0.f;

    const int wm = (warp >> 2) * 64;   // warp M offset (2 rows)
    const int wn = (warp & 3) * 32;    // warp N offset (4 cols)

    // ---- hoisted ldmatrix base offsets (s-independent part) ----
    uint32_t aoff[4], boff[2];
#pragma unroll
    for (int mi = 0; mi < 4; mi++) {
        const uint32_t row = (uint32_t)(wm + mi * 16 + (lane & 15));
        const uint32_t cc = ((uint32_t)lane >> 4) << 4;
        aoff[mi] = row * 128u + (cc ^ ((row & 7u) << 4));
    }
#pragma unroll
    for (int nj = 0; nj < 2; nj++) {
        const uint32_t row = (uint32_t)(wn + nj * 16 + (lane >> 4) * 8 + (lane & 7));
        const uint32_t cc = (((uint32_t)lane >> 3) & 1u) << 4;
        boff[nj] = row * 128u + (cc ^ ((row & 7u) << 4));
    }

    // SMSP-distinct skew phase: warps w and w+4 share a scheduler; offset them.
    const int ph = (warp + (warp >> 2)) & 3;

    load_stage();
    load_stage();

    uint32_t st_rd = 0;   // read-stage byte offset (rotates like stoff)
    for (int kc = 0; kc < NKC; kc++) {
        if (kc + 1 < NKC) {
            asm volatile("cp.async.wait_group 1;\n" ::);
        } else {
            asm volatile("cp.async.wait_group 0;\n" ::);
        }
        __syncthreads();

        const uint32_t Ab = sbase + st_rd;
        const uint32_t Bb = Ab + A_STAGE_BYTES;
        st_rd = (st_rd == 2 * STAGE_BYTES) ? 0u : st_rd + STAGE_BYTES;
        const bool prefetch = (kc + 2 < NKC);
#pragma unroll
        for (int si = 0; si < 4; si++) {       // k16 steps, warp-skewed order
            const uint32_t sx = (uint32_t)(((si + ph) & 3) << 5);
            uint32_t a[4][4];
#pragma unroll
            for (int mi = 0; mi < 4; mi++)
                ldm_x4(a[mi][0], a[mi][1], a[mi][2], a[mi][3], Ab + (aoff[mi] ^ sx));
            uint32_t b[4][2];
#pragma unroll
            for (int nj = 0; nj < 2; nj++)
                ldm_x4(b[nj * 2][0], b[nj * 2][1], b[nj * 2 + 1][0], b[nj * 2 + 1][1],
                       Bb + (boff[nj] ^ sx));
#pragma unroll
            for (int mi = 0; mi < 4; mi++)
#pragma unroll
                for (int ni = 0; ni < 4; ni++)
                    mma_fp16(acc[mi][ni], a[mi], b[ni]);

            // deferred next-stage issue, split into two half-bursts so the
            // per-warp LSU queue spike is halved. Stage being overwritten was
            // last read at iter kc-1; every warp has passed the barrier above
            // since, so this is race-free.
            if (si == 0 && prefetch) load_half_A();
            if (si == 1 && prefetch) load_half_B();
        }
    }

    // ---- store fp16 partials for this split ----
    __half* P = g_Ph + (size_t)blockIdx.z * NN * NCOL;
    const int lr = lane >> 2;
    const int lc = lane & 3;
#pragma unroll
    for (int mi = 0; mi < 4; mi++) {
        const int row0 = m0 + wm + mi * 16 + lr;
        const int row1 = row0 + 8;
#pragma unroll
        for (int ni = 0; ni < 4; ni++) {
            const int col = n0 + wn + ni * 8 + lc * 2;
            const __half2 h0 = __floats2half2_rn(acc[mi][ni][0], acc[mi][ni][1]);
            const __half2 h1 = __floats2half2_rn(acc[mi][ni][2], acc[mi][ni][3]);
            *reinterpret_cast<__half2*>(&P[(size_t)row0 * NCOL + col]) = h0;
            *reinterpret_cast<__half2*>(&P[(size_t)row1 * NCOL + col]) = h1;
        }
    }
}

// ---------------------------------------------------------------------------
// Kernel 3: out = (P0 + P1 + P2) * inv_deg + bias   (self-loop is inside A+I)
// ---------------------------------------------------------------------------
__global__ void combine_kernel(const float* __restrict__ bias, float* __restrict__ out) {
    __shared__ float biasS[32];
    if (threadIdx.x < 32) biasS[threadIdx.x] = bias[threadIdx.x];
    __syncthreads();
    const int idx = blockIdx.x * blockDim.x + threadIdx.x;     // 4-col group index
    const int row = idx / (NCOL / 4);
    const int c4  = (idx % (NCOL / 4)) * 4;
    const size_t off = (size_t)row * NCOL + c4;
    const __half2* p0 = reinterpret_cast<const __half2*>(g_Ph + off);
    const __half2* p1 = reinterpret_cast<const __half2*>(g_Ph + (size_t)NN * NCOL + off);
    const __half2* p2 = reinterpret_cast<const __half2*>(g_Ph + 2 * (size_t)NN * NCOL + off);
    const float id = g_invdeg[row];
    float4 o;
    {
        const float2 a = __half22float2(p0[0]);
        const float2 b = __half22float2(p1[0]);
        const float2 c = __half22float2(p2[0]);
        o.x = (a.x + b.x + c.x) * id + biasS[(c4 + 0) & 31];
        o.y = (a.y + b.y + c.y) * id + biasS[(c4 + 1) & 31];
    }
    {
        const float2 a = __half22float2(p0[1]);
        const float2 b = __half22float2(p1[1]);
        const float2 c = __half22float2(p2[1]);
        o.z = (a.x + b.x + c.x) * id + biasS[(c4 + 2) & 31];
        o.w = (a.y + b.y + c.y) * id + biasS[(c4 + 3) & 31];
    }
    *reinterpret_cast<float4*>(out + off) = o;
}

// ---------------------------------------------------------------------------
extern "C" void kernel_launch(void* const* d_in, const int* in_sizes, int n_in,
                              void* d_out, int out_size) {
    const float* X    = (const float*)d_in[0];   // node_feats [8192,24,32]
    const float* adj  = (const float*)d_in[1];   // adj_matrix [8192,8192]
    const float* W    = (const float*)d_in[2];   // weight [32,32]
    const float* bias = (const float*)d_in[3];   // bias [32]
    float* out = (float*)d_out;

    cudaFuncSetAttribute(gemm_kernel, cudaFuncAttributeMaxDynamicSharedMemorySize,
                         SMEM_BYTES);

    pre_kernel<<<NN + 256, 256>>>(adj, X, W);
    gemm_kernel<<<dim3(NCOL / BN, NN / BM, NSPLIT), THREADS, SMEM_BYTES>>>(out);
    combine_kernel<<<(NN * NCOL / 4) / 256, 256>>>(bias, out);
}